// round 1
// baseline (speedup 1.0000x reference)
#include <cuda_runtime.h>
#include <cuda_bf16.h>
#include <cstdint>

// Problem constants (InfoNCELoss: N=8192, D=256)
static constexpr int N = 8192;
static constexpr int D = 256;
static constexpr float INV_T = 14.285714285714286f;        // 1/0.07
static constexpr float K1 = 20.609929156f;                  // log2(e)/0.07
// exp(d/T - 1/T) = exp2f(d*K1 - K1)

static constexpr int BM = 128;
static constexpr int BN = 128;
static constexpr int NSPLIT = 2;                            // column splits
static constexpr int SKP = D + 8;                           // smem row stride (elems), pad vs bank conflicts
static constexpr int SMEM_BYTES = (BM + BN) * SKP * 2;      // bf16

// Scratch (device globals: allocation-free rule)
__device__ __nv_bfloat16 g_un[N * D];
__device__ __nv_bfloat16 g_vn[N * D];
__device__ float g_diag[N];
__device__ float g_S[NSPLIT * N];

// ---------------------------------------------------------------------------
// Kernel 1: row-normalize u and v -> bf16; diag_i = dot(un_i, vn_i) in fp32
// ---------------------------------------------------------------------------
__global__ void normalize_kernel(const float* __restrict__ u,
                                 const float* __restrict__ v) {
    int row = blockIdx.x;
    int t = threadIdx.x;                 // 256 threads == D
    size_t idx = (size_t)row * D + t;
    float uu = u[idx];
    float vv = v[idx];
    float su = uu * uu, sv = vv * vv, suv = uu * vv;

    // warp reduce
    #pragma unroll
    for (int o = 16; o > 0; o >>= 1) {
        su  += __shfl_xor_sync(0xffffffffu, su, o);
        sv  += __shfl_xor_sync(0xffffffffu, sv, o);
        suv += __shfl_xor_sync(0xffffffffu, suv, o);
    }
    __shared__ float sh[3][8];
    int lane = t & 31, w = t >> 5;
    if (lane == 0) { sh[0][w] = su; sh[1][w] = sv; sh[2][w] = suv; }
    __syncthreads();
    su = 0.f; sv = 0.f; suv = 0.f;
    #pragma unroll
    for (int i = 0; i < 8; i++) { su += sh[0][i]; sv += sh[1][i]; suv += sh[2][i]; }

    float nu = fmaxf(sqrtf(su), 1e-8f);
    float nv = fmaxf(sqrtf(sv), 1e-8f);
    g_un[idx] = __float2bfloat16(uu / nu);
    g_vn[idx] = __float2bfloat16(vv / nv);
    if (t == 0) g_diag[row] = suv / (nu * nv);
}

// ---------------------------------------------------------------------------
// Kernel 2: fused GEMM + exp + row-sum.
// grid = (N/BM, NSPLIT). CTA computes rows [bx*BM, +BM) vs cols
// [split*(N/NSPLIT) .. +N/NSPLIT), accumulating S_row = sum_j exp(d/T - 1/T).
// 8 warps: 4 (m) x 2 (n); warp tile 32x64; mma.sync m16n8k16 bf16->f32.
// ---------------------------------------------------------------------------
__device__ __forceinline__ void mma16816(float c[4], const uint32_t a[4],
                                         const uint32_t b[2]) {
    asm volatile(
        "mma.sync.aligned.m16n8k16.row.col.f32.bf16.bf16.f32 "
        "{%0,%1,%2,%3}, {%4,%5,%6,%7}, {%8,%9}, {%0,%1,%2,%3};\n"
        : "+f"(c[0]), "+f"(c[1]), "+f"(c[2]), "+f"(c[3])
        : "r"(a[0]), "r"(a[1]), "r"(a[2]), "r"(a[3]), "r"(b[0]), "r"(b[1]));
}

__global__ __launch_bounds__(256, 1) void gemm_lse_kernel() {
    extern __shared__ char smem[];
    __nv_bfloat16* As = reinterpret_cast<__nv_bfloat16*>(smem);          // BM x SKP
    __nv_bfloat16* Bs = As + BM * SKP;                                   // BN x SKP

    const int t = threadIdx.x;
    const int lane = t & 31;
    const int warp = t >> 5;
    const int wm = warp & 3;       // 0..3 (m)
    const int wn = warp >> 2;      // 0..1 (n)
    const int gid = lane >> 2;     // 0..7
    const int tig = lane & 3;      // 0..3

    const int row0 = blockIdx.x * BM;
    const int split = blockIdx.y;
    const int col_base0 = split * (N / NSPLIT);
    const int NTILES = (N / NSPLIT) / BN;

    // Load A block (BM x D bf16), vectorized 16B
    {
        const uint4* src = reinterpret_cast<const uint4*>(&g_un[(size_t)row0 * D]);
        #pragma unroll
        for (int i = t; i < BM * D / 8; i += 256) {
            int r = i / (D / 8);
            int k8 = (i % (D / 8)) * 8;
            *reinterpret_cast<uint4*>(&As[r * SKP + k8]) = src[i];
        }
    }

    float rsum[4] = {0.f, 0.f, 0.f, 0.f};  // rows: mi*16 + {gid, gid+8}

    for (int jt = 0; jt < NTILES; ++jt) {
        if (jt > 0) __syncthreads();   // previous tile's readers done
        // Load B tile (BN x D bf16)
        {
            const uint4* src = reinterpret_cast<const uint4*>(
                &g_vn[(size_t)(col_base0 + jt * BN) * D]);
            #pragma unroll
            for (int i = t; i < BN * D / 8; i += 256) {
                int r = i / (D / 8);
                int k8 = (i % (D / 8)) * 8;
                *reinterpret_cast<uint4*>(&Bs[r * SKP + k8]) = src[i];
            }
        }
        __syncthreads();

        float c[2][8][4];
        #pragma unroll
        for (int mi = 0; mi < 2; mi++)
            #pragma unroll
            for (int ni = 0; ni < 8; ni++)
                #pragma unroll
                for (int q = 0; q < 4; q++) c[mi][ni][q] = 0.f;

        #pragma unroll 4
        for (int k0 = 0; k0 < D; k0 += 16) {
            uint32_t a[2][4];
            #pragma unroll
            for (int mi = 0; mi < 2; mi++) {
                int rb = wm * 32 + mi * 16;
                a[mi][0] = *reinterpret_cast<const uint32_t*>(&As[(rb + gid) * SKP + k0 + 2 * tig]);
                a[mi][1] = *reinterpret_cast<const uint32_t*>(&As[(rb + gid + 8) * SKP + k0 + 2 * tig]);
                a[mi][2] = *reinterpret_cast<const uint32_t*>(&As[(rb + gid) * SKP + k0 + 8 + 2 * tig]);
                a[mi][3] = *reinterpret_cast<const uint32_t*>(&As[(rb + gid + 8) * SKP + k0 + 8 + 2 * tig]);
            }
            uint32_t b[8][2];
            #pragma unroll
            for (int ni = 0; ni < 8; ni++) {
                int cb = wn * 64 + ni * 8 + gid;
                b[ni][0] = *reinterpret_cast<const uint32_t*>(&Bs[cb * SKP + k0 + 2 * tig]);
                b[ni][1] = *reinterpret_cast<const uint32_t*>(&Bs[cb * SKP + k0 + 8 + 2 * tig]);
            }
            #pragma unroll
            for (int mi = 0; mi < 2; mi++)
                #pragma unroll
                for (int ni = 0; ni < 8; ni++)
                    mma16816(c[mi][ni], a[mi], b[ni]);
        }

        // Epilogue: exp(d/T - 1/T) = exp2(d*K1 - K1), accumulate per-row sums
        #pragma unroll
        for (int mi = 0; mi < 2; mi++) {
            #pragma unroll
            for (int ni = 0; ni < 8; ni++) {
                float e0 = exp2f(fmaf(c[mi][ni][0], K1, -K1));
                float e1 = exp2f(fmaf(c[mi][ni][1], K1, -K1));
                float e2 = exp2f(fmaf(c[mi][ni][2], K1, -K1));
                float e3 = exp2f(fmaf(c[mi][ni][3], K1, -K1));
                rsum[mi * 2 + 0] += e0 + e1;   // row gid
                rsum[mi * 2 + 1] += e2 + e3;   // row gid+8
            }
        }
    }

    // Reduce across the 4 lanes (tig) sharing a row
    #pragma unroll
    for (int x = 0; x < 4; x++) {
        rsum[x] += __shfl_xor_sync(0xffffffffu, rsum[x], 1);
        rsum[x] += __shfl_xor_sync(0xffffffffu, rsum[x], 2);
    }

    __syncthreads();   // done with As/Bs; reuse smem
    float* Ssum = reinterpret_cast<float*>(smem);   // [2][BM]
    if (tig == 0) {
        #pragma unroll
        for (int mi = 0; mi < 2; mi++)
            #pragma unroll
            for (int h = 0; h < 2; h++) {
                int r = wm * 32 + mi * 16 + h * 8 + gid;
                Ssum[wn * BM + r] = rsum[mi * 2 + h];
            }
    }
    __syncthreads();
    if (t < BM) {
        float S = Ssum[t] + Ssum[BM + t];
        g_S[split * N + row0 + t] = S;
    }
}

// ---------------------------------------------------------------------------
// Kernel 3: loss = mean(log(S0+S1) + (1 - diag)/T)
// ---------------------------------------------------------------------------
__global__ void finalize_kernel(float* __restrict__ out) {
    int t = threadIdx.x;
    float acc = 0.f;
    for (int i = t; i < N; i += 256) {
        float S = g_S[i] + g_S[N + i];
        acc += logf(S) + (1.0f - g_diag[i]) * INV_T;
    }
    #pragma unroll
    for (int o = 16; o > 0; o >>= 1) acc += __shfl_xor_sync(0xffffffffu, acc, o);
    __shared__ float sh[8];
    int lane = t & 31, w = t >> 5;
    if (lane == 0) sh[w] = acc;
    __syncthreads();
    if (t == 0) {
        float total = 0.f;
        #pragma unroll
        for (int i = 0; i < 8; i++) total += sh[i];
        out[0] = total / (float)N;
    }
}

// ---------------------------------------------------------------------------
extern "C" void kernel_launch(void* const* d_in, const int* in_sizes, int n_in,
                              void* d_out, int out_size) {
    const float* u = (const float*)d_in[0];
    const float* v = (const float*)d_in[1];
    float* out = (float*)d_out;

    cudaFuncSetAttribute(gemm_lse_kernel,
                         cudaFuncAttributeMaxDynamicSharedMemorySize, SMEM_BYTES);

    normalize_kernel<<<N, 256>>>(u, v);
    dim3 grid(N / BM, NSPLIT);
    gemm_lse_kernel<<<grid, 256, SMEM_BYTES>>>();
    finalize_kernel<<<1, 256>>>(out);
}

// round 3
// speedup vs baseline: 1.9227x; 1.9227x over previous
#include <cuda_runtime.h>
#include <cuda_bf16.h>
#include <cstdint>

// Problem: InfoNCELoss, N=8192, D=256
static constexpr int N = 8192;
static constexpr int D = 256;
static constexpr float INV_T = 14.285714285714286f;   // 1/0.07
static constexpr float K1 = 20.609929156f;            // log2(e)/0.07
// exp((d-1)/T) = exp2(d*K1 - K1); valid since cos <= 1 (fixed-max trick)

static constexpr int BM = 128;
static constexpr int BN = 128;
static constexpr int NSPLIT = 2;
static constexpr int NTILES = (N / NSPLIT) / BN;      // 32

// Smem tile: 128 rows x 256 bf16 = 128 x 512B rows, XOR-swizzled 16B chunks.
static constexpr int ROW_BYTES = 512;
static constexpr int TILE_BYTES = BM * ROW_BYTES;     // 65536
static constexpr int SMEM_A  = 0;
static constexpr int SMEM_B0 = TILE_BYTES;
static constexpr int SMEM_B1 = 2 * TILE_BYTES;
static constexpr int SMEM_TOTAL = 3 * TILE_BYTES;     // 196608 B

// Scratch (device globals: allocation-free rule)
__device__ __align__(128) __nv_bfloat16 g_un[N * D];
__device__ __align__(128) __nv_bfloat16 g_vn[N * D];
__device__ float g_diag[N];
__device__ float g_S[NSPLIT * N];

// ---------------------------------------------------------------------------
// helpers
// ---------------------------------------------------------------------------
__device__ __forceinline__ uint32_t smem_u32(const void* p) {
    uint32_t a;
    asm("{ .reg .u64 t; cvta.to.shared.u64 t, %1; cvt.u32.u64 %0, t; }"
        : "=r"(a) : "l"(p));
    return a;
}

// swizzled byte offset of 16B chunk c in row r (c in 0..31)
__device__ __forceinline__ uint32_t swz(uint32_t r, uint32_t c) {
    return r * ROW_BYTES + (((c & ~7u) | ((c ^ r) & 7u)) << 4);
}

__device__ __forceinline__ void ldsm_x4(uint32_t& r0, uint32_t& r1,
                                        uint32_t& r2, uint32_t& r3, uint32_t a) {
    asm volatile("ldmatrix.sync.aligned.m8n8.x4.shared.b16 {%0,%1,%2,%3}, [%4];"
                 : "=r"(r0), "=r"(r1), "=r"(r2), "=r"(r3) : "r"(a));
}

__device__ __forceinline__ void mma16816(float c[4], const uint32_t a[4],
                                         const uint32_t b[2]) {
    asm volatile(
        "mma.sync.aligned.m16n8k16.row.col.f32.bf16.bf16.f32 "
        "{%0,%1,%2,%3}, {%4,%5,%6,%7}, {%8,%9}, {%0,%1,%2,%3};\n"
        : "+f"(c[0]), "+f"(c[1]), "+f"(c[2]), "+f"(c[3])
        : "r"(a[0]), "r"(a[1]), "r"(a[2]), "r"(a[3]), "r"(b[0]), "r"(b[1]));
}

// cp.async one 128x256 bf16 tile into swizzled layout; 256 threads, 16 chunks each
__device__ __forceinline__ void load_tile(uint32_t smem_base,
                                          const __nv_bfloat16* gsrc, int t) {
    #pragma unroll
    for (int i = 0; i < 16; i++) {
        int idx = t + i * 256;           // 0..4095 16B chunks
        uint32_t r = (uint32_t)idx >> 5; // row 0..127
        uint32_t c = (uint32_t)idx & 31; // chunk in row
        uint32_t dst = smem_base + swz(r, c);
        const void* src = reinterpret_cast<const char*>(gsrc) + (size_t)idx * 16;
        asm volatile("cp.async.cg.shared.global [%0], [%1], 16;\n"
                     :: "r"(dst), "l"(src) : "memory");
    }
}

// ---------------------------------------------------------------------------
// Kernel 1: row-normalize (warp per row): bf16 normalized outputs + fp32 diag
// ---------------------------------------------------------------------------
__device__ __forceinline__ uint32_t pack_bf2(float x, float y) {
    __nv_bfloat162 h = __float22bfloat162_rn(make_float2(x, y));
    return *reinterpret_cast<uint32_t*>(&h);
}

__global__ void normalize_kernel(const float* __restrict__ u,
                                 const float* __restrict__ v) {
    int t = threadIdx.x, w = t >> 5, lane = t & 31;
    int row = blockIdx.x * 8 + w;
    const float4* u4 = reinterpret_cast<const float4*>(u + (size_t)row * D);
    const float4* v4 = reinterpret_cast<const float4*>(v + (size_t)row * D);
    float4 a0 = u4[lane * 2], a1 = u4[lane * 2 + 1];
    float4 b0 = v4[lane * 2], b1 = v4[lane * 2 + 1];

    float su = a0.x*a0.x + a0.y*a0.y + a0.z*a0.z + a0.w*a0.w
             + a1.x*a1.x + a1.y*a1.y + a1.z*a1.z + a1.w*a1.w;
    float sv = b0.x*b0.x + b0.y*b0.y + b0.z*b0.z + b0.w*b0.w
             + b1.x*b1.x + b1.y*b1.y + b1.z*b1.z + b1.w*b1.w;
    float sd = a0.x*b0.x + a0.y*b0.y + a0.z*b0.z + a0.w*b0.w
             + a1.x*b1.x + a1.y*b1.y + a1.z*b1.z + a1.w*b1.w;
    #pragma unroll
    for (int o = 16; o > 0; o >>= 1) {
        su += __shfl_xor_sync(0xffffffffu, su, o);
        sv += __shfl_xor_sync(0xffffffffu, sv, o);
        sd += __shfl_xor_sync(0xffffffffu, sd, o);
    }
    float rnu = 1.0f / fmaxf(sqrtf(su), 1e-8f);
    float rnv = 1.0f / fmaxf(sqrtf(sv), 1e-8f);

    uint4 pu, pv;
    pu.x = pack_bf2(a0.x*rnu, a0.y*rnu); pu.y = pack_bf2(a0.z*rnu, a0.w*rnu);
    pu.z = pack_bf2(a1.x*rnu, a1.y*rnu); pu.w = pack_bf2(a1.z*rnu, a1.w*rnu);
    pv.x = pack_bf2(b0.x*rnv, b0.y*rnv); pv.y = pack_bf2(b0.z*rnv, b0.w*rnv);
    pv.z = pack_bf2(b1.x*rnv, b1.y*rnv); pv.w = pack_bf2(b1.z*rnv, b1.w*rnv);
    *reinterpret_cast<uint4*>(&g_un[(size_t)row * D + lane * 8]) = pu;
    *reinterpret_cast<uint4*>(&g_vn[(size_t)row * D + lane * 8]) = pv;
    if (lane == 0) g_diag[row] = sd * rnu * rnv;
}

// ---------------------------------------------------------------------------
// Kernel 2: fused GEMM + exp + row-sum (mma.sync + ldmatrix + cp.async pipe).
// grid (N/BM, NSPLIT). 8 warps: wm=warp&3 (m), wn=warp>>2 (n); warp tile 32x64.
// ---------------------------------------------------------------------------
__global__ __launch_bounds__(256, 1) void gemm_lse_kernel() {
    extern __shared__ char smem[];
    uint32_t sb = smem_u32(smem);

    const int t = threadIdx.x;
    const int lane = t & 31;
    const int warp = t >> 5;
    const int wm = warp & 3;
    const int wn = warp >> 2;
    const int gid = lane >> 2;
    const int tig = lane & 3;

    const int row0 = blockIdx.x * BM;
    const int col0 = blockIdx.y * (N / NSPLIT);

    // Prologue: A once + B0 + B1
    load_tile(sb + SMEM_A, &g_un[(size_t)row0 * D], t);
    asm volatile("cp.async.commit_group;" ::: "memory");
    load_tile(sb + SMEM_B0, &g_vn[(size_t)col0 * D], t);
    asm volatile("cp.async.commit_group;" ::: "memory");
    load_tile(sb + SMEM_B1, &g_vn[(size_t)(col0 + BN) * D], t);
    asm volatile("cp.async.commit_group;" ::: "memory");

    // Precomputed per-lane ldmatrix addressing components
    // A: row = rb + (lane&15), chunk = 2k + (lane>>4)
    const uint32_t a_row[2] = { (uint32_t)(wm * 32 + (lane & 15)),
                                (uint32_t)(wm * 32 + 16 + (lane & 15)) };
    const uint32_t a_d = (uint32_t)(lane >> 4);
    // B: n = cb + q*16 + ((lane&16)>>1) + (lane&7), chunk = 2k + ((lane>>3)&1)
    const uint32_t b_nbase = (uint32_t)(wn * 64 + ((lane & 16) >> 1) + (lane & 7));
    const uint32_t b_d = (uint32_t)((lane >> 3) & 1);

    float rsum[4] = {0.f, 0.f, 0.f, 0.f};   // rows mi*16 + {gid, gid+8}

    #pragma unroll 1
    for (int j = 0; j < NTILES; j++) {
        asm volatile("cp.async.wait_group 1;" ::: "memory");
        __syncthreads();

        const uint32_t bsm = sb + ((j & 1) ? SMEM_B1 : SMEM_B0);

        float c[2][8][4];
        #pragma unroll
        for (int mi = 0; mi < 2; mi++)
            #pragma unroll
            for (int ni = 0; ni < 8; ni++)
                #pragma unroll
                for (int q = 0; q < 4; q++) c[mi][ni][q] = 0.f;

        #pragma unroll
        for (int k = 0; k < 16; k++) {
            const uint32_t chA = 2 * k + a_d;
            const uint32_t chB = 2 * k + b_d;
            uint32_t a[2][4];
            #pragma unroll
            for (int mi = 0; mi < 2; mi++)
                ldsm_x4(a[mi][0], a[mi][1], a[mi][2], a[mi][3],
                        sb + SMEM_A + swz(a_row[mi], chA));
            uint32_t b[8][2];
            #pragma unroll
            for (int q = 0; q < 4; q++) {
                uint32_t r0, r1, r2, r3;
                ldsm_x4(r0, r1, r2, r3, bsm + swz(b_nbase + q * 16, chB));
                b[q * 2 + 0][0] = r0; b[q * 2 + 0][1] = r1;
                b[q * 2 + 1][0] = r2; b[q * 2 + 1][1] = r3;
            }
            #pragma unroll
            for (int mi = 0; mi < 2; mi++)
                #pragma unroll
                for (int ni = 0; ni < 8; ni++)
                    mma16816(c[mi][ni], a[mi], b[ni]);
        }

        __syncthreads();   // everyone done reading B slot (j&1)

        // prefetch tile j+2 into the slot we just freed
        if (j + 2 < NTILES)
            load_tile(sb + ((j & 1) ? SMEM_B1 : SMEM_B0),
                      &g_vn[(size_t)(col0 + (j + 2) * BN) * D], t);
        asm volatile("cp.async.commit_group;" ::: "memory");

        // epilogue: exp2(d*K1 - K1), accumulate row sums (overlaps prefetch)
        #pragma unroll
        for (int mi = 0; mi < 2; mi++) {
            #pragma unroll
            for (int ni = 0; ni < 8; ni++) {
                rsum[mi * 2 + 0] += exp2f(fmaf(c[mi][ni][0], K1, -K1))
                                  + exp2f(fmaf(c[mi][ni][1], K1, -K1));
                rsum[mi * 2 + 1] += exp2f(fmaf(c[mi][ni][2], K1, -K1))
                                  + exp2f(fmaf(c[mi][ni][3], K1, -K1));
            }
        }
    }

    // Reduce across the 4 lanes (tig) sharing each row
    #pragma unroll
    for (int x = 0; x < 4; x++) {
        rsum[x] += __shfl_xor_sync(0xffffffffu, rsum[x], 1);
        rsum[x] += __shfl_xor_sync(0xffffffffu, rsum[x], 2);
    }

    __syncthreads();   // done with smem tiles; reuse A region
    float* Ssum = reinterpret_cast<float*>(smem);   // [2][BM]
    if (tig == 0) {
        #pragma unroll
        for (int mi = 0; mi < 2; mi++)
            #pragma unroll
            for (int h = 0; h < 2; h++) {
                int r = wm * 32 + mi * 16 + h * 8 + gid;
                Ssum[wn * BM + r] = rsum[mi * 2 + h];
            }
    }
    __syncthreads();
    if (t < BM)
        g_S[blockIdx.y * N + row0 + t] = Ssum[t] + Ssum[BM + t];
}

// ---------------------------------------------------------------------------
// Kernel 3: loss = mean(log(S0+S1) + (1 - diag)/T)
// ---------------------------------------------------------------------------
__global__ void finalize_kernel(float* __restrict__ out) {
    int t = threadIdx.x;
    float acc = 0.0f;
    for (int i = t; i < N; i += 1024) {
        float S = g_S[i] + g_S[N + i];
        acc += logf(S) + (1.0f - g_diag[i]) * INV_T;
    }
    #pragma unroll
    for (int o = 16; o > 0; o >>= 1) acc += __shfl_xor_sync(0xffffffffu, acc, o);
    __shared__ float sh[32];
    int lane = t & 31, w = t >> 5;
    if (lane == 0) sh[w] = acc;
    __syncthreads();
    if (t == 0) {
        float total = 0.0f;
        #pragma unroll
        for (int i = 0; i < 32; i++) total += sh[i];
        out[0] = total / (float)N;
    }
}

// ---------------------------------------------------------------------------
extern "C" void kernel_launch(void* const* d_in, const int* in_sizes, int n_in,
                              void* d_out, int out_size) {
    const float* u = (const float*)d_in[0];
    const float* v = (const float*)d_in[1];
    float* out = (float*)d_out;

    cudaFuncSetAttribute(gemm_lse_kernel,
                         cudaFuncAttributeMaxDynamicSharedMemorySize, SMEM_TOTAL);

    normalize_kernel<<<N / 8, 256>>>(u, v);
    dim3 grid(N / BM, NSPLIT);
    gemm_lse_kernel<<<grid, 256, SMEM_TOTAL>>>();
    finalize_kernel<<<1, 1024>>>(out);
}

// round 4
// speedup vs baseline: 1.9531x; 1.0158x over previous
#include <cuda_runtime.h>
#include <cuda_bf16.h>
#include <cstdint>

// Problem: InfoNCELoss, N=8192, D=256
static constexpr int N = 8192;
static constexpr int D = 256;
static constexpr float INV_T = 14.285714285714286f;   // 1/0.07
static constexpr float K1 = 20.609929156f;            // log2(e)/0.07
// exp((d-1)/T) = exp2(d*K1 - K1); valid since cos <= 1 (fixed-max trick)

static constexpr int BM = 256;
static constexpr int BN = 128;
static constexpr int NSPLIT = 4;
static constexpr int NTILES = (N / NSPLIT) / BN;      // 16
static constexpr int NHALVES = NTILES * 2;            // 32

// A: 256 rows x 256 bf16 (512B rows) resident = 128 KB
// B: two half-K buffers, each 128 rows x 128 bf16 (256B rows) = 32 KB
static constexpr int A_ROW_BYTES = 512;
static constexpr int B_ROW_BYTES = 256;
static constexpr int SMEM_A  = 0;
static constexpr int A_BYTES = BM * A_ROW_BYTES;          // 131072
static constexpr int B_BYTES = BN * B_ROW_BYTES;          // 32768
static constexpr int SMEM_B0 = A_BYTES;
static constexpr int SMEM_B1 = A_BYTES + B_BYTES;
static constexpr int SMEM_TOTAL = A_BYTES + 2 * B_BYTES;  // 196608

// Scratch (device globals: allocation-free rule)
__device__ __align__(128) __nv_bfloat16 g_un[N * D];
__device__ __align__(128) __nv_bfloat16 g_vn[N * D];
__device__ float g_diag[N];
__device__ float g_S[NSPLIT * N];

// ---------------------------------------------------------------------------
// helpers
// ---------------------------------------------------------------------------
__device__ __forceinline__ uint32_t smem_u32(const void* p) {
    uint32_t a;
    asm("{ .reg .u64 t; cvta.to.shared.u64 t, %1; cvt.u32.u64 %0, t; }"
        : "=r"(a) : "l"(p));
    return a;
}

// swizzled byte offsets; chunk c is a 16B unit within the row
__device__ __forceinline__ uint32_t swzA(uint32_t r, uint32_t c) {   // c in 0..31
    return r * A_ROW_BYTES + (((c & ~7u) | ((c ^ r) & 7u)) << 4);
}
__device__ __forceinline__ uint32_t swzB(uint32_t r, uint32_t c) {   // c in 0..15
    return r * B_ROW_BYTES + (((c & ~7u) | ((c ^ r) & 7u)) << 4);
}

__device__ __forceinline__ void ldsm_x4(uint32_t& r0, uint32_t& r1,
                                        uint32_t& r2, uint32_t& r3, uint32_t a) {
    asm volatile("ldmatrix.sync.aligned.m8n8.x4.shared.b16 {%0,%1,%2,%3}, [%4];"
                 : "=r"(r0), "=r"(r1), "=r"(r2), "=r"(r3) : "r"(a));
}

__device__ __forceinline__ void mma16816(float c[4], const uint32_t a[4],
                                         const uint32_t b[2]) {
    asm volatile(
        "mma.sync.aligned.m16n8k16.row.col.f32.bf16.bf16.f32 "
        "{%0,%1,%2,%3}, {%4,%5,%6,%7}, {%8,%9}, {%0,%1,%2,%3};\n"
        : "+f"(c[0]), "+f"(c[1]), "+f"(c[2]), "+f"(c[3])
        : "r"(a[0]), "r"(a[1]), "r"(a[2]), "r"(a[3]), "r"(b[0]), "r"(b[1]));
}

// Load resident A tile: 256 rows x 512B, 8192 chunks, 32 per thread
__device__ __forceinline__ void load_A(uint32_t smem_base,
                                       const __nv_bfloat16* gsrc, int t) {
    #pragma unroll
    for (int i = 0; i < 32; i++) {
        int idx = t + i * 256;
        uint32_t r = (uint32_t)idx >> 5;
        uint32_t c = (uint32_t)idx & 31;
        uint32_t dst = smem_base + swzA(r, c);
        const void* src = reinterpret_cast<const char*>(gsrc) + (size_t)idx * 16;
        asm volatile("cp.async.cg.shared.global [%0], [%1], 16;\n"
                     :: "r"(dst), "l"(src) : "memory");
    }
}

// Load one B half-tile: 128 rows x 256B (half of K), 2048 chunks, 8 per thread.
// gsrc points at the first row of the B tile (full 512B rows); h selects K half.
__device__ __forceinline__ void load_B_half(uint32_t smem_base,
                                            const __nv_bfloat16* gsrc,
                                            int h, int t) {
    #pragma unroll
    for (int i = 0; i < 8; i++) {
        int idx = t + i * 256;
        uint32_t r = (uint32_t)idx >> 4;   // row 0..127
        uint32_t c = (uint32_t)idx & 15;   // chunk in half-row
        uint32_t dst = smem_base + swzB(r, c);
        const void* src = reinterpret_cast<const char*>(gsrc)
                        + (size_t)r * A_ROW_BYTES + (size_t)h * 256 + (size_t)c * 16;
        asm volatile("cp.async.cg.shared.global [%0], [%1], 16;\n"
                     :: "r"(dst), "l"(src) : "memory");
    }
}

// ---------------------------------------------------------------------------
// Kernel 1: row-normalize (warp per row): bf16 normalized outputs + fp32 diag
// ---------------------------------------------------------------------------
__device__ __forceinline__ uint32_t pack_bf2(float x, float y) {
    __nv_bfloat162 h = __float22bfloat162_rn(make_float2(x, y));
    return *reinterpret_cast<uint32_t*>(&h);
}

__global__ void normalize_kernel(const float* __restrict__ u,
                                 const float* __restrict__ v) {
    int t = threadIdx.x, w = t >> 5, lane = t & 31;
    int row = blockIdx.x * 8 + w;
    const float4* u4 = reinterpret_cast<const float4*>(u + (size_t)row * D);
    const float4* v4 = reinterpret_cast<const float4*>(v + (size_t)row * D);
    float4 a0 = u4[lane * 2], a1 = u4[lane * 2 + 1];
    float4 b0 = v4[lane * 2], b1 = v4[lane * 2 + 1];

    float su = a0.x*a0.x + a0.y*a0.y + a0.z*a0.z + a0.w*a0.w
             + a1.x*a1.x + a1.y*a1.y + a1.z*a1.z + a1.w*a1.w;
    float sv = b0.x*b0.x + b0.y*b0.y + b0.z*b0.z + b0.w*b0.w
             + b1.x*b1.x + b1.y*b1.y + b1.z*b1.z + b1.w*b1.w;
    float sd = a0.x*b0.x + a0.y*b0.y + a0.z*b0.z + a0.w*b0.w
             + a1.x*b1.x + a1.y*b1.y + a1.z*b1.z + a1.w*b1.w;
    #pragma unroll
    for (int o = 16; o > 0; o >>= 1) {
        su += __shfl_xor_sync(0xffffffffu, su, o);
        sv += __shfl_xor_sync(0xffffffffu, sv, o);
        sd += __shfl_xor_sync(0xffffffffu, sd, o);
    }
    float rnu = 1.0f / fmaxf(sqrtf(su), 1e-8f);
    float rnv = 1.0f / fmaxf(sqrtf(sv), 1e-8f);

    uint4 pu, pv;
    pu.x = pack_bf2(a0.x*rnu, a0.y*rnu); pu.y = pack_bf2(a0.z*rnu, a0.w*rnu);
    pu.z = pack_bf2(a1.x*rnu, a1.y*rnu); pu.w = pack_bf2(a1.z*rnu, a1.w*rnu);
    pv.x = pack_bf2(b0.x*rnv, b0.y*rnv); pv.y = pack_bf2(b0.z*rnv, b0.w*rnv);
    pv.z = pack_bf2(b1.x*rnv, b1.y*rnv); pv.w = pack_bf2(b1.z*rnv, b1.w*rnv);
    *reinterpret_cast<uint4*>(&g_un[(size_t)row * D + lane * 8]) = pu;
    *reinterpret_cast<uint4*>(&g_vn[(size_t)row * D + lane * 8]) = pv;
    if (lane == 0) g_diag[row] = sd * rnu * rnv;
}

// ---------------------------------------------------------------------------
// Kernel 2: fused GEMM + exp + row-sum.
// grid (N/BM, NSPLIT) = (32, 4). 8 warps: wm=warp&3 (m), wn=warp>>2 (n).
// Warp tile 64x64; A resident in smem, B double-buffered per half-K.
// ---------------------------------------------------------------------------
__global__ __launch_bounds__(256, 1) void gemm_lse_kernel() {
    extern __shared__ char smem[];
    uint32_t sb = smem_u32(smem);

    const int t = threadIdx.x;
    const int lane = t & 31;
    const int warp = t >> 5;
    const int wm = warp & 3;
    const int wn = warp >> 2;
    const int gid = lane >> 2;
    const int tig = lane & 3;

    const int row0 = blockIdx.x * BM;
    const int col0 = blockIdx.y * (N / NSPLIT);

    // Prologue: A + tile0 halves
    load_A(sb + SMEM_A, &g_un[(size_t)row0 * D], t);
    asm volatile("cp.async.commit_group;" ::: "memory");
    load_B_half(sb + SMEM_B0, &g_vn[(size_t)col0 * D], 0, t);
    asm volatile("cp.async.commit_group;" ::: "memory");
    load_B_half(sb + SMEM_B1, &g_vn[(size_t)col0 * D], 1, t);
    asm volatile("cp.async.commit_group;" ::: "memory");

    // ldmatrix lane addressing
    const uint32_t a_rbase = (uint32_t)(wm * 64 + (lane & 15));
    const uint32_t a_d = (uint32_t)(lane >> 4);
    const uint32_t b_nbase = (uint32_t)(wn * 64 + ((lane & 16) >> 1) + (lane & 7));
    const uint32_t b_d = (uint32_t)((lane >> 3) & 1);

    float rsum[8];
    #pragma unroll
    for (int i = 0; i < 8; i++) rsum[i] = 0.f;

    #pragma unroll 1
    for (int j = 0; j < NTILES; j++) {
        float c[4][8][4];
        #pragma unroll
        for (int mi = 0; mi < 4; mi++)
            #pragma unroll
            for (int ni = 0; ni < 8; ni++)
                #pragma unroll
                for (int q = 0; q < 4; q++) c[mi][ni][q] = 0.f;

        #pragma unroll
        for (int h = 0; h < 2; h++) {
            asm volatile("cp.async.wait_group 1;" ::: "memory");
            __syncthreads();
            const uint32_t bsm = sb + (h ? SMEM_B1 : SMEM_B0);

            #pragma unroll
            for (int kk = 0; kk < 8; kk++) {
                const int k = h * 8 + kk;
                const uint32_t chA = 2 * k + a_d;
                const uint32_t chB = 2 * kk + b_d;
                uint32_t a[4][4];
                #pragma unroll
                for (int mi = 0; mi < 4; mi++)
                    ldsm_x4(a[mi][0], a[mi][1], a[mi][2], a[mi][3],
                            sb + SMEM_A + swzA(a_rbase + mi * 16, chA));
                uint32_t b[8][2];
                #pragma unroll
                for (int q = 0; q < 4; q++) {
                    uint32_t r0, r1, r2, r3;
                    ldsm_x4(r0, r1, r2, r3, bsm + swzB(b_nbase + q * 16, chB));
                    b[q * 2 + 0][0] = r0; b[q * 2 + 0][1] = r1;
                    b[q * 2 + 1][0] = r2; b[q * 2 + 1][1] = r3;
                }
                #pragma unroll
                for (int mi = 0; mi < 4; mi++)
                    #pragma unroll
                    for (int ni = 0; ni < 8; ni++)
                        mma16816(c[mi][ni], a[mi], b[ni]);
            }

            __syncthreads();   // done reading buffer h

            // prefetch next half (global half index 2j + h + 2) into buffer h
            const int nh = 2 * j + h + 2;
            if (nh < NHALVES)
                load_B_half(sb + (h ? SMEM_B1 : SMEM_B0),
                            &g_vn[(size_t)(col0 + (nh >> 1) * BN) * D],
                            nh & 1, t);
            asm volatile("cp.async.commit_group;" ::: "memory");
        }

        // epilogue: exp2(d*K1 - K1), accumulate row sums (overlaps prefetch)
        #pragma unroll
        for (int mi = 0; mi < 4; mi++) {
            #pragma unroll
            for (int ni = 0; ni < 8; ni++) {
                rsum[mi * 2 + 0] += exp2f(fmaf(c[mi][ni][0], K1, -K1))
                                  + exp2f(fmaf(c[mi][ni][1], K1, -K1));
                rsum[mi * 2 + 1] += exp2f(fmaf(c[mi][ni][2], K1, -K1))
                                  + exp2f(fmaf(c[mi][ni][3], K1, -K1));
            }
        }
    }

    // Reduce across the 4 lanes (tig) sharing each row
    #pragma unroll
    for (int x = 0; x < 8; x++) {
        rsum[x] += __shfl_xor_sync(0xffffffffu, rsum[x], 1);
        rsum[x] += __shfl_xor_sync(0xffffffffu, rsum[x], 2);
    }

    __syncthreads();   // done with smem tiles; reuse A region
    float* Ssum = reinterpret_cast<float*>(smem);   // [2][BM]
    if (tig == 0) {
        #pragma unroll
        for (int mi = 0; mi < 4; mi++)
            #pragma unroll
            for (int hh = 0; hh < 2; hh++) {
                int r = wm * 64 + mi * 16 + hh * 8 + gid;
                Ssum[wn * BM + r] = rsum[mi * 2 + hh];
            }
    }
    __syncthreads();
    g_S[blockIdx.y * N + row0 + t] = Ssum[t] + Ssum[BM + t];
}

// ---------------------------------------------------------------------------
// Kernel 3: loss = mean(log(sum_s S[s]) + (1 - diag)/T)
// ---------------------------------------------------------------------------
__global__ void finalize_kernel(float* __restrict__ out) {
    int t = threadIdx.x;
    float acc = 0.0f;
    for (int i = t; i < N; i += 1024) {
        float S = g_S[i] + g_S[N + i] + g_S[2 * N + i] + g_S[3 * N + i];
        acc += logf(S) + (1.0f - g_diag[i]) * INV_T;
    }
    #pragma unroll
    for (int o = 16; o > 0; o >>= 1) acc += __shfl_xor_sync(0xffffffffu, acc, o);
    __shared__ float sh[32];
    int lane = t & 31, w = t >> 5;
    if (lane == 0) sh[w] = acc;
    __syncthreads();
    if (t == 0) {
        float total = 0.0f;
        #pragma unroll
        for (int i = 0; i < 32; i++) total += sh[i];
        out[0] = total / (float)N;
    }
}

// ---------------------------------------------------------------------------
extern "C" void kernel_launch(void* const* d_in, const int* in_sizes, int n_in,
                              void* d_out, int out_size) {
    const float* u = (const float*)d_in[0];
    const float* v = (const float*)d_in[1];
    float* out = (float*)d_out;

    cudaFuncSetAttribute(gemm_lse_kernel,
                         cudaFuncAttributeMaxDynamicSharedMemorySize, SMEM_TOTAL);

    normalize_kernel<<<N / 8, 256>>>(u, v);
    dim3 grid(N / BM, NSPLIT);
    gemm_lse_kernel<<<grid, 256, SMEM_TOTAL>>>();
    finalize_kernel<<<1, 1024>>>(out);
}